// round 7
// baseline (speedup 1.0000x reference)
#include <cuda_runtime.h>
#include <cstdint>

#define NBLOCKS   592
#define NTHREADS  256
#define TOTALT    (NBLOCKS * NTHREADS)               // 151552
#define B_ROWS    4000000
#define RPT       ((B_ROWS + TOTALT - 1) / TOTALT)   // 27
#define T1CAP     8                                   // pass-1a evals (detect T<=7)
#define T2CAP     24                                  // fallback extension limit
#define C100      144.2695040888963f                 // 100 * log2(e)
#define SUM_TOL   4000.0f                            // B_ROWS * 1e-3

// ---- device-global state (reset by stk_init each launch -> graph-replay safe) ----
__device__ double       g_facc[T2CAP];
__device__ unsigned int g_count;
__device__ unsigned int g_release;
__device__ float        g_th5[B_ROWS];   // theta after 5 Newton steps
__device__ float        g_th7[B_ROWS];   // theta after 7 Newton steps

__global__ void stk_init() {
    int i = threadIdx.x;
    for (int j = i; j < T2CAP; j += blockDim.x) g_facc[j] = 0.0;
    if (i == 0) { g_count = 0u; g_release = 0u; }
}

// Phase-counted software grid barrier; grid fully co-resident
// (<=64 regs, 4 blk/SM * 148 SMs = 592 blocks).
__device__ __forceinline__ void grid_barrier(int phase) {
    __syncthreads();
    if (threadIdx.x == 0) {
        __threadfence();
        unsigned arrived = atomicAdd(&g_count, 1u) + 1u;
        unsigned want = (unsigned)(phase + 1);
        if (arrived == (unsigned)NBLOCKS * want) {
            atomicExch(&g_release, want);
        } else {
            volatile unsigned* rel = &g_release;
            while (*rel < want) { __nanosleep(64); }
        }
        __threadfence();
    }
    __syncthreads();
}

// 3rd largest of 8 == sorted[:, -3]   (identical to the R5-proven version)
__device__ __forceinline__ float theta0_of(const float v[8]) {
    float t1 = -3.4e38f, t2 = -3.4e38f, t3 = -3.4e38f;
#pragma unroll
    for (int j = 0; j < 8; j++) {
        float x = v[j];
        if (x > t1)      { t3 = t2; t2 = t1; t1 = x; }
        else if (x > t2) { t3 = t2; t2 = x; }
        else if (x > t3) { t3 = x; }
    }
    return t3;
}

// All 8 stable sigmoids at (unscaled) theta, paired reciprocals.
// EXACT copy of the R5 arithmetic (rel_err 2.1e-7 measured).
__device__ __forceinline__ void sig8(const float v[8], float th, float m[8]) {
    float th144 = th * C100;
#pragma unroll
    for (int j = 0; j < 8; j += 2) {
        float x0 = __fmaf_rn(v[j],     C100, -th144);
        float x1 = __fmaf_rn(v[j + 1], C100, -th144);
        float e0 = exp2f(-fabsf(x0));          // in (0,1], never overflows
        float e1 = exp2f(-fabsf(x1));
        float a0 = 1.0f + e0;
        float a1 = 1.0f + e1;
        float R  = __fdividef(1.0f, a0 * a1);
        float n0 = (x0 >= 0.0f) ? 1.0f : e0;
        float n1 = (x1 >= 0.0f) ? 1.0f : e1;
        m[j]     = n0 * a1 * R;
        m[j + 1] = n1 * a0 * R;
    }
}

// f = sum(m) - 2 ; d = sum m*(1-m)   (R5-exact)
__device__ __forceinline__ void eval8(const float v[8], float th, float& f, float& d) {
    float m[8];
    sig8(v, th, m);
    float sm = 0.0f, dd = 0.0f;
#pragma unroll
    for (int j = 0; j < 8; j++) {
        sm += m[j];
        dd += __fmaf_rn(-m[j], m[j], m[j]);
    }
    f = sm - 2.0f;
    d = dd;
}

__device__ __forceinline__ float newton_adv(const float v[8], float th, float& f_out) {
    float f, d;
    eval8(v, th, f, d);
    f_out = f;
    float step = (d > 0.0f) ? 0.01f * __fdividef(f, d) : 0.0f;
    return th + step;
}

__device__ __forceinline__ void load_row(const float* __restrict__ s, unsigned r,
                                         float v[8]) {
    const float4* p = reinterpret_cast<const float4*>(s) + (size_t)r * 2;
    float4 va = p[0];
    float4 vb = p[1];
    v[0]=va.x; v[1]=va.y; v[2]=va.z; v[3]=va.w;
    v[4]=vb.x; v[5]=vb.y; v[6]=vb.z; v[7]=vb.w;
}

__global__ void __launch_bounds__(NTHREADS, 4)
stk_fused(const float* __restrict__ s, float* __restrict__ out) {
    __shared__ float s_facc[T2CAP];
    __shared__ int   s_T;

    const int tid  = threadIdx.x;
    const int lane = tid & 31;
    const unsigned gt = blockIdx.x * NTHREADS + tid;

    for (int j = tid; j < T2CAP; j += NTHREADS) s_facc[j] = 0.0f;
    __syncthreads();

    // ========= PASS 1a: uniform 8-step Newton, f sums + theta planes @5,@7 =========
    float facc[T1CAP];
#pragma unroll
    for (int t = 0; t < T1CAP; t++) facc[t] = 0.0f;

    for (int i = 0; i < RPT; i++) {
        unsigned r = gt + (unsigned)i * TOTALT;
        bool valid = (r < B_ROWS);

        float v[8];
        if (valid) {
            load_row(s, r, v);
        } else {
            // dummy row: f == 0, d == 0 -> step 0 forever, contributes nothing
            v[0] = v[1] = 1e30f;
#pragma unroll
            for (int j = 2; j < 8; j++) v[j] = -1e30f;
        }

        float th = theta0_of(v);          // theta_0

#pragma unroll
        for (int t = 0; t < T1CAP; t++) {
            if (t == 5 && valid) g_th5[r] = th;   // theta_5
            if (t == 7 && valid) g_th7[r] = th;   // theta_7
            float f;
            th = newton_adv(v, th, f);
            facc[t] += f;
        }
    }

    // ---- one block reduction of facc[] ----
#pragma unroll
    for (int t = 0; t < T1CAP; t++) {
        float w = facc[t];
#pragma unroll
        for (int o = 16; o > 0; o >>= 1) w += __shfl_down_sync(0xffffffffu, w, o);
        if (lane == 0) atomicAdd(&s_facc[t], w);
    }
    __syncthreads();
    for (int j = tid; j < T1CAP; j += NTHREADS)
        atomicAdd(&g_facc[j], (double)s_facc[j]);

    grid_barrier(0);

    // ========= global stop iteration T (uniform across all blocks) =========
    if (tid == 0) {
        volatile double* fa = g_facc;
        int T = -1;
        for (int t = 0; t < T1CAP; t++) {
            if (fa[t] < (double)SUM_TOL) { T = t; break; }
        }
        s_T = T;
    }
    __syncthreads();
    int T = s_T;

    // ========= COLD fallback: T > 7 (not expected for this input) =========
    if (T < 0) {
        for (int j = tid; j < T2CAP; j += NTHREADS) s_facc[j] = 0.0f;
        __syncthreads();

        float facc2[T2CAP - T1CAP];
#pragma unroll
        for (int t = 0; t < T2CAP - T1CAP; t++) facc2[t] = 0.0f;

        for (int i = 0; i < RPT; i++) {
            unsigned r = gt + (unsigned)i * TOTALT;
            if (r >= B_ROWS) continue;
            float v[8];
            load_row(s, r, v);
            float th = g_th7[r];
            // advance to theta_8 first (theta_7 -> one step)
            float f;
            th = newton_adv(v, th, f);
#pragma unroll
            for (int t = 0; t < T2CAP - T1CAP; t++) {
                th = newton_adv(v, th, f);        // eval at theta_{8+t}
                facc2[t] += f;
            }
        }
#pragma unroll
        for (int t = 0; t < T2CAP - T1CAP; t++) {
            float w = facc2[t];
#pragma unroll
            for (int o = 16; o > 0; o >>= 1) w += __shfl_down_sync(0xffffffffu, w, o);
            if (lane == 0) atomicAdd(&s_facc[t], w);
        }
        __syncthreads();
        for (int j = tid; j < T2CAP - T1CAP; j += NTHREADS)
            atomicAdd(&g_facc[T1CAP + j], (double)s_facc[j]);

        grid_barrier(1);

        if (tid == 0) {
            volatile double* fa = g_facc;
            int TT = T2CAP - 1;
            for (int t = T1CAP; t < T2CAP; t++) {
                if (fa[t] < (double)SUM_TOL) { TT = t; break; }
            }
            s_T = TT;
        }
        __syncthreads();
        T = s_T;
    }

    // checkpoint plane selection (uniform)
    const float* plane;
    int p;
    if      (T >= 7) { plane = g_th7; p = 7; }
    else if (T >= 5) { plane = g_th5; p = 5; }
    else             { plane = 0;     p = 0; }

    // ========= PASS 2: resume from checkpoint + output =========
    for (int i = 0; i < RPT; i++) {
        unsigned r = gt + (unsigned)i * TOTALT;
        if (r >= B_ROWS) break;
        float v[8];
        load_row(s, r, v);

        float th = plane ? plane[r] : theta0_of(v);
        for (int t = p; t < T; t++) {
            float f;
            th = newton_adv(v, th, f);
        }

        float m[8];
        sig8(v, th, m);
        float4* q = reinterpret_cast<float4*>(out) + (size_t)r * 2;
        __stcs(q,     make_float4(m[0], m[1], m[2], m[3]));
        __stcs(q + 1, make_float4(m[4], m[5], m[6], m[7]));
    }
}

extern "C" void kernel_launch(void* const* d_in, const int* in_sizes, int n_in,
                              void* d_out, int out_size) {
    (void)in_sizes; (void)n_in; (void)out_size;
    const float* s = (const float*)d_in[0];
    float* out = (float*)d_out;

    stk_init<<<1, 256>>>();
    stk_fused<<<NBLOCKS, NTHREADS>>>(s, out);
}

// round 8
// speedup vs baseline: 2.5869x; 2.5869x over previous
#include <cuda_runtime.h>
#include <cstdint>

#define NBLOCKS   592
#define NTHREADS  256
#define TOTALT    (NBLOCKS * NTHREADS)               // 151552
#define B_ROWS    4000000
#define RPT       ((B_ROWS + TOTALT - 1) / TOTALT)   // 27
#define T1CAP     8                                   // pass-1 evals (detect T<=7)
#define T2CAP     24                                  // cold fallback limit
#define C100      144.2695040888963f                 // 100 * log2(e)
#define SUM_TOL   4000.0                             // B_ROWS * 1e-3

// ---- device-global state (reset by stk_init each launch -> graph-replay safe) ----
__device__ double       g_facc[T2CAP];
__device__ unsigned int g_count;
__device__ unsigned int g_release;
__device__ float        g_th5[B_ROWS];   // theta after 5 Newton steps
__device__ float        g_th6[B_ROWS];   // theta after 6 Newton steps

__global__ void stk_init() {
    int i = threadIdx.x;
    for (int j = i; j < T2CAP; j += blockDim.x) g_facc[j] = 0.0;
    if (i == 0) { g_count = 0u; g_release = 0u; }
}

// Phase-counted software grid barrier; grid fully co-resident
// (<=64 regs via launch bounds, 4 blk/SM * 148 SMs = 592 blocks).
__device__ __forceinline__ void grid_barrier(int phase) {
    __syncthreads();
    if (threadIdx.x == 0) {
        __threadfence();
        unsigned arrived = atomicAdd(&g_count, 1u) + 1u;
        unsigned want = (unsigned)(phase + 1);
        if (arrived == (unsigned)NBLOCKS * want) {
            atomicExch(&g_release, want);
        } else {
            volatile unsigned* rel = &g_release;
            while (*rel < want) { __nanosleep(64); }
        }
        __threadfence();
    }
    __syncthreads();
}

// 3rd largest of 8 == sorted[:, -3]
__device__ __forceinline__ float theta0_of(const float v[8]) {
    float t1 = -3.4e38f, t2 = -3.4e38f, t3 = -3.4e38f;
#pragma unroll
    for (int j = 0; j < 8; j++) {
        float x = v[j];
        if (x > t1)      { t3 = t2; t2 = t1; t1 = x; }
        else if (x > t2) { t3 = t2; t2 = x; }
        else if (x > t3) { t3 = x; }
    }
    return t3;
}

// All 8 stable sigmoids, paired reciprocals. R5-exact arithmetic (2.1e-7 proven).
__device__ __forceinline__ void sig8(const float v[8], float th, float m[8]) {
    float th144 = th * C100;
#pragma unroll
    for (int j = 0; j < 8; j += 2) {
        float x0 = __fmaf_rn(v[j],     C100, -th144);
        float x1 = __fmaf_rn(v[j + 1], C100, -th144);
        float e0 = exp2f(-fabsf(x0));          // in (0,1], never overflows
        float e1 = exp2f(-fabsf(x1));
        float a0 = 1.0f + e0;
        float a1 = 1.0f + e1;
        float R  = __fdividef(1.0f, a0 * a1);
        float n0 = (x0 >= 0.0f) ? 1.0f : e0;
        float n1 = (x1 >= 0.0f) ? 1.0f : e1;
        m[j]     = n0 * a1 * R;
        m[j + 1] = n1 * a0 * R;
    }
}

// f = sum(m) - 2 ; d = sum m*(1-m)
__device__ __forceinline__ void eval8(const float v[8], float th, float& f, float& d) {
    float m[8];
    sig8(v, th, m);
    float sm = 0.0f, dd = 0.0f;
#pragma unroll
    for (int j = 0; j < 8; j++) {
        sm += m[j];
        dd += __fmaf_rn(-m[j], m[j], m[j]);
    }
    f = sm - 2.0f;
    d = dd;
}

__device__ __forceinline__ float newton_adv(const float v[8], float th, float& f_out) {
    float f, d;
    eval8(v, th, f, d);
    f_out = f;
    float step = (d > 0.0f) ? 0.01f * __fdividef(f, d) : 0.0f;
    return th + step;
}

__device__ __forceinline__ void load_row(const float* __restrict__ s, unsigned r,
                                         float v[8]) {
    const float4* p = reinterpret_cast<const float4*>(s) + (size_t)r * 2;
    float4 va = p[0];
    float4 vb = p[1];
    v[0]=va.x; v[1]=va.y; v[2]=va.z; v[3]=va.w;
    v[4]=vb.x; v[5]=vb.y; v[6]=vb.z; v[7]=vb.w;
}

__global__ void __launch_bounds__(NTHREADS, 4)
stk_fused(const float* __restrict__ s, float* __restrict__ out) {
    __shared__ float s_facc[T2CAP];
    __shared__ int   s_T;

    const int tid  = threadIdx.x;
    const int lane = tid & 31;
    const unsigned gt = blockIdx.x * NTHREADS + tid;

    for (int j = tid; j < T2CAP; j += NTHREADS) s_facc[j] = 0.0f;
    __syncthreads();

    // ======= PASS 1: uniform 8-step Newton, valid-predicated f sums, planes @5,@6 =======
    float facc[T1CAP];
#pragma unroll
    for (int t = 0; t < T1CAP; t++) facc[t] = 0.0f;

    for (int i = 0; i < RPT; i++) {
        unsigned r = gt + (unsigned)i * TOTALT;
        bool valid = (r < B_ROWS);
        unsigned rr = valid ? r : (B_ROWS - 1);   // dummy lanes recompute last row

        float v[8];
        load_row(s, rr, v);

        float th = theta0_of(v);          // theta_0

#pragma unroll
        for (int t = 0; t < T1CAP; t++) {
            if (t == 5 && valid) g_th5[r] = th;   // theta_5
            if (t == 6 && valid) g_th6[r] = th;   // theta_6
            float f;
            th = newton_adv(v, th, f);
            if (valid) facc[t] += f;      // CRITICAL: dummy rows contribute 0
        }
    }

    // ---- one block reduction of facc[] ----
#pragma unroll
    for (int t = 0; t < T1CAP; t++) {
        float w = facc[t];
#pragma unroll
        for (int o = 16; o > 0; o >>= 1) w += __shfl_down_sync(0xffffffffu, w, o);
        if (lane == 0) atomicAdd(&s_facc[t], w);
    }
    __syncthreads();
    for (int j = tid; j < T1CAP; j += NTHREADS)
        atomicAdd(&g_facc[j], (double)s_facc[j]);

    grid_barrier(0);

    // ======= global stop iteration T (uniform across all blocks) =======
    if (tid == 0) {
        volatile double* fa = g_facc;
        int T = -1;
        for (int t = 0; t < T1CAP; t++) {
            if (fa[t] < SUM_TOL) { T = t; break; }   // mean<1e-3 <=> sum<4000
        }
        s_T = T;
    }
    __syncthreads();
    int T = s_T;

    // ======= COLD fallback: T > 7 (not expected; kept for safety) =======
    if (T < 0) {
        for (int j = tid; j < T2CAP; j += NTHREADS) s_facc[j] = 0.0f;
        __syncthreads();

        float facc2[T2CAP - T1CAP];
#pragma unroll
        for (int t = 0; t < T2CAP - T1CAP; t++) facc2[t] = 0.0f;

        for (int i = 0; i < RPT; i++) {
            unsigned r = gt + (unsigned)i * TOTALT;
            if (r >= B_ROWS) continue;
            float v[8];
            load_row(s, r, v);
            float th = g_th6[r];                  // theta_6
            float f;
            th = newton_adv(v, th, f);            // -> theta_7
            th = newton_adv(v, th, f);            // -> theta_8
#pragma unroll
            for (int t = 0; t < T2CAP - T1CAP; t++) {
                th = newton_adv(v, th, f);        // f = f(theta_{8+t})
                facc2[t] += f;
            }
        }
#pragma unroll
        for (int t = 0; t < T2CAP - T1CAP; t++) {
            float w = facc2[t];
#pragma unroll
            for (int o = 16; o > 0; o >>= 1) w += __shfl_down_sync(0xffffffffu, w, o);
            if (lane == 0) atomicAdd(&s_facc[t], w);
        }
        __syncthreads();
        for (int j = tid; j < T2CAP - T1CAP; j += NTHREADS)
            atomicAdd(&g_facc[T1CAP + j], (double)s_facc[j]);

        grid_barrier(1);

        if (tid == 0) {
            volatile double* fa = g_facc;
            int TT = T2CAP - 1;
            for (int t = T1CAP; t < T2CAP; t++) {
                if (fa[t] < SUM_TOL) { TT = t; break; }
            }
            s_T = TT;
        }
        __syncthreads();
        T = s_T;
    }

    // checkpoint plane selection (uniform)
    const float* plane;
    int p;
    if      (T >= 6) { plane = g_th6; p = 6; }
    else if (T == 5) { plane = g_th5; p = 5; }
    else             { plane = 0;     p = 0; }

    // ======= PASS 2: resume from checkpoint (0-1 evals typical) + output =======
    for (int i = 0; i < RPT; i++) {
        unsigned r = gt + (unsigned)i * TOTALT;
        if (r >= B_ROWS) break;
        float v[8];
        load_row(s, r, v);

        float th = plane ? __ldcs(plane + r) : theta0_of(v);
        for (int t = p; t < T; t++) {
            float f;
            th = newton_adv(v, th, f);
        }

        float m[8];
        sig8(v, th, m);
        float4* q = reinterpret_cast<float4*>(out) + (size_t)r * 2;
        __stcs(q,     make_float4(m[0], m[1], m[2], m[3]));
        __stcs(q + 1, make_float4(m[4], m[5], m[6], m[7]));
    }
}

extern "C" void kernel_launch(void* const* d_in, const int* in_sizes, int n_in,
                              void* d_out, int out_size) {
    (void)in_sizes; (void)n_in; (void)out_size;
    const float* s = (const float*)d_in[0];
    float* out = (float*)d_out;

    stk_init<<<1, 256>>>();
    stk_fused<<<NBLOCKS, NTHREADS>>>(s, out);
}

// round 11
// speedup vs baseline: 2.7170x; 1.0503x over previous
// R11 == R10 resubmission: R10's failure was infra ("system not yet initialized"
// = cudaErrorSystemNotReady raised inside _harness_main.cu before kernel_launch
// was ever called). No kernel-side signal; re-benching the same source.
#include <cuda_runtime.h>
#include <cstdint>

#define NBLOCKS   592
#define NTHREADS  256
#define TOTALT    (NBLOCKS * NTHREADS)               // 151552
#define B_ROWS    4000000
#define RPT       ((B_ROWS + TOTALT - 1) / TOTALT)   // 27
#define T1CAP     7                                   // pass-1 evals (detect T<=6)
#define T2CAP     24                                  // cold fallback limit
#define C100      144.2695040888963f                 // 100 * log2(e)
#define SUM_TOL   4000.0                             // B_ROWS * 1e-3

// ---- device-global state (reset by stk_init each launch -> graph-replay safe) ----
__device__ double       g_facc[T2CAP];
__device__ unsigned int g_count;
__device__ unsigned int g_release;
__device__ float        g_th5[B_ROWS];   // theta after 5 Newton steps
__device__ float        g_th6[B_ROWS];   // theta after 6 Newton steps

__global__ void stk_init() {
    int i = threadIdx.x;
    for (int j = i; j < T2CAP; j += blockDim.x) g_facc[j] = 0.0;
    if (i == 0) { g_count = 0u; g_release = 0u; }
}

// Phase-counted software grid barrier; grid fully co-resident
// (<=64 regs via launch bounds, 4 blk/SM * 148 SMs = 592 blocks).
__device__ __forceinline__ void grid_barrier(int phase) {
    __syncthreads();
    if (threadIdx.x == 0) {
        __threadfence();
        unsigned arrived = atomicAdd(&g_count, 1u) + 1u;
        unsigned want = (unsigned)(phase + 1);
        if (arrived == (unsigned)NBLOCKS * want) {
            atomicExch(&g_release, want);
        } else {
            volatile unsigned* rel = &g_release;
            while (*rel < want) { __nanosleep(64); }
        }
        __threadfence();
    }
    __syncthreads();
}

// Single-instruction MUFU ops (accuracy class identical to __expf/__fdividef internals).
__device__ __forceinline__ float ex2a(float x) {
    float y; asm("ex2.approx.f32 %0, %1;" : "=f"(y) : "f"(x)); return y;
}
__device__ __forceinline__ float rcpa(float x) {
    float y; asm("rcp.approx.f32 %0, %1;" : "=f"(y) : "f"(x)); return y;
}

// 3rd largest of 8 == sorted[:, -3], branch-free FMNMX network.
__device__ __forceinline__ float theta0_of(const float v[8]) {
    float t1 = -3.4e38f, t2 = -3.4e38f, t3 = -3.4e38f;
#pragma unroll
    for (int j = 0; j < 8; j++) {
        float x  = v[j];
        float l1 = fminf(t1, x);  t1 = fmaxf(t1, x);
        float l2 = fminf(t2, l1); t2 = fmaxf(t2, l1);
        t3 = fmaxf(t3, l2);
    }
    return t3;
}

// 8 stable sigmoids, SELECT form (proven: a in [1,2], no overflow/subnormal paths),
// pair-shared reciprocals, single-MUFU ex2/rcp.
//   e = 2^(-|x|) in [0,1];  m = (x>=0 ? 1 : e) / (1+e)
__device__ __forceinline__ void sig8(const float v[8], float th, float m[8]) {
    float th144 = th * C100;
#pragma unroll
    for (int j = 0; j < 8; j += 2) {
        float x0 = __fmaf_rn(v[j],     C100, -th144);
        float x1 = __fmaf_rn(v[j + 1], C100, -th144);
        float e0 = ex2a(fminf(x0, -x0));       // 2^(-|x0|), FTZ to 0 for |x|>126
        float e1 = ex2a(fminf(x1, -x1));
        float a0 = 1.0f + e0;                  // in [1,2]
        float a1 = 1.0f + e1;
        float R  = rcpa(a0 * a1);              // product in [1,4]: always safe
        float n0 = (x0 >= 0.0f) ? 1.0f : e0;
        float n1 = (x1 >= 0.0f) ? 1.0f : e1;
        m[j]     = n0 * (a1 * R);
        m[j + 1] = n1 * (a0 * R);
    }
}

// f = sum(m) - 2 ; d = sum m*(1-m)
__device__ __forceinline__ void eval8(const float v[8], float th, float& f, float& d) {
    float m[8];
    sig8(v, th, m);
    float sm = 0.0f, dd = 0.0f;
#pragma unroll
    for (int j = 0; j < 8; j++) {
        sm += m[j];
        dd += __fmaf_rn(-m[j], m[j], m[j]);
    }
    f = sm - 2.0f;
    d = dd;
}

__device__ __forceinline__ float newton_adv(const float v[8], float th, float& f_out) {
    float f, d;
    eval8(v, th, f, d);
    f_out = f;
    float step = (d > 0.0f) ? 0.01f * (f * rcpa(d)) : 0.0f;
    return th + step;
}

__device__ __forceinline__ void load_row(const float* __restrict__ s, unsigned r,
                                         float v[8]) {
    const float4* p = reinterpret_cast<const float4*>(s) + (size_t)r * 2;
    float4 va = p[0];
    float4 vb = p[1];
    v[0]=va.x; v[1]=va.y; v[2]=va.z; v[3]=va.w;
    v[4]=vb.x; v[5]=vb.y; v[6]=vb.z; v[7]=vb.w;
}

__global__ void __launch_bounds__(NTHREADS, 4)
stk_fused(const float* __restrict__ s, float* __restrict__ out) {
    __shared__ float s_facc[T2CAP];
    __shared__ int   s_T;

    const int tid  = threadIdx.x;
    const int lane = tid & 31;
    const unsigned gt = blockIdx.x * NTHREADS + tid;

    for (int j = tid; j < T2CAP; j += NTHREADS) s_facc[j] = 0.0f;
    __syncthreads();

    // ======= PASS 1: uniform 7-step Newton, valid-predicated f sums, planes @5,@6 =======
    float facc[T1CAP];
#pragma unroll
    for (int t = 0; t < T1CAP; t++) facc[t] = 0.0f;

    for (int i = 0; i < RPT; i++) {
        unsigned r = gt + (unsigned)i * TOTALT;
        bool valid = (r < B_ROWS);
        unsigned rr = valid ? r : (B_ROWS - 1);   // tail lanes recompute last row

        float v[8];
        load_row(s, rr, v);

        float th = theta0_of(v);          // theta_0

#pragma unroll
        for (int t = 0; t < T1CAP; t++) {
            if (t == 5 && valid) g_th5[r] = th;   // theta_5
            if (t == 6 && valid) g_th6[r] = th;   // theta_6
            float f;
            th = newton_adv(v, th, f);
            if (valid) facc[t] += f;      // tail lanes contribute exactly 0
        }
    }

    // ---- one block reduction of facc[] ----
#pragma unroll
    for (int t = 0; t < T1CAP; t++) {
        float w = facc[t];
#pragma unroll
        for (int o = 16; o > 0; o >>= 1) w += __shfl_down_sync(0xffffffffu, w, o);
        if (lane == 0) atomicAdd(&s_facc[t], w);
    }
    __syncthreads();
    for (int j = tid; j < T1CAP; j += NTHREADS)
        atomicAdd(&g_facc[j], (double)s_facc[j]);

    grid_barrier(0);

    // ======= global stop iteration T (uniform across all blocks) =======
    if (tid == 0) {
        volatile double* fa = g_facc;
        int T = -1;
        for (int t = 0; t < T1CAP; t++) {
            if (fa[t] < SUM_TOL) { T = t; break; }   // mean<1e-3 <=> sum<4000
        }
        s_T = T;
    }
    __syncthreads();
    int T = s_T;

    // ======= COLD fallback: T > 6 (not expected; kept for safety) =======
    if (T < 0) {
        for (int j = tid; j < T2CAP; j += NTHREADS) s_facc[j] = 0.0f;
        __syncthreads();

        float facc2[T2CAP - T1CAP];
#pragma unroll
        for (int t = 0; t < T2CAP - T1CAP; t++) facc2[t] = 0.0f;

        for (int i = 0; i < RPT; i++) {
            unsigned r = gt + (unsigned)i * TOTALT;
            if (r >= B_ROWS) continue;
            float v[8];
            load_row(s, r, v);
            float th = g_th6[r];                  // theta_6
            float f;
            th = newton_adv(v, th, f);            // f(theta_6) already summed; -> theta_7
#pragma unroll
            for (int t = 0; t < T2CAP - T1CAP; t++) {
                th = newton_adv(v, th, f);        // f = f(theta_{7+t})
                facc2[t] += f;
            }
        }
#pragma unroll
        for (int t = 0; t < T2CAP - T1CAP; t++) {
            float w = facc2[t];
#pragma unroll
            for (int o = 16; o > 0; o >>= 1) w += __shfl_down_sync(0xffffffffu, w, o);
            if (lane == 0) atomicAdd(&s_facc[t], w);
        }
        __syncthreads();
        for (int j = tid; j < T2CAP - T1CAP; j += NTHREADS)
            atomicAdd(&g_facc[T1CAP + j], (double)s_facc[j]);

        grid_barrier(1);

        if (tid == 0) {
            volatile double* fa = g_facc;
            int TT = T2CAP - 1;
            for (int t = T1CAP; t < T2CAP; t++) {
                if (fa[t] < SUM_TOL) { TT = t; break; }
            }
            s_T = TT;
        }
        __syncthreads();
        T = s_T;
    }

    // checkpoint plane selection (uniform)
    const float* plane;
    int p;
    if      (T >= 6) { plane = g_th6; p = 6; }
    else if (T == 5) { plane = g_th5; p = 5; }
    else             { plane = 0;     p = 0; }

    // ======= PASS 2: resume from checkpoint (0 evals when T=6) + output =======
    for (int i = 0; i < RPT; i++) {
        unsigned r = gt + (unsigned)i * TOTALT;
        if (r >= B_ROWS) break;
        float v[8];
        load_row(s, r, v);

        float th = plane ? __ldcs(plane + r) : theta0_of(v);
        for (int t = p; t < T; t++) {
            float f;
            th = newton_adv(v, th, f);
        }

        float m[8];
        sig8(v, th, m);
        float4* q = reinterpret_cast<float4*>(out) + (size_t)r * 2;
        __stcs(q,     make_float4(m[0], m[1], m[2], m[3]));
        __stcs(q + 1, make_float4(m[4], m[5], m[6], m[7]));
    }
}

extern "C" void kernel_launch(void* const* d_in, const int* in_sizes, int n_in,
                              void* d_out, int out_size) {
    (void)in_sizes; (void)n_in; (void)out_size;
    const float* s = (const float*)d_in[0];
    float* out = (float*)d_out;

    stk_init<<<1, 256>>>();
    stk_fused<<<NBLOCKS, NTHREADS>>>(s, out);
}

// round 12
// speedup vs baseline: 3.0163x; 1.1102x over previous
#include <cuda_runtime.h>
#include <cstdint>

#define NBLOCKS   592
#define NTHREADS  256
#define TOTALT    (NBLOCKS * NTHREADS)               // 151552
#define B_ROWS    4000000
#define RPT       ((B_ROWS + TOTALT - 1) / TOTALT)   // 27
#define T1CAP     7                                   // pass-1 evals (detect T<=6)
#define T2CAP     24                                  // cold fallback limit
#define C100      144.2695040888963f                 // 100 * log2(e)
#define SUM_TOL   4000.0                             // B_ROWS * 1e-3

// ---- device-global state (reset by stk_init each launch -> graph-replay safe) ----
__device__ double       g_facc[T2CAP];
__device__ unsigned int g_count;
__device__ unsigned int g_release;
__device__ float        g_th5[B_ROWS];   // theta after 5 Newton steps
__device__ float        g_th6[B_ROWS];   // theta after 6 Newton steps

__global__ void stk_init() {
    int i = threadIdx.x;
    for (int j = i; j < T2CAP; j += blockDim.x) g_facc[j] = 0.0;
    if (i == 0) { g_count = 0u; g_release = 0u; }
}

// Phase-counted software grid barrier; grid fully co-resident
// (<=64 regs via launch bounds, 4 blk/SM * 148 SMs = 592 blocks).
__device__ __forceinline__ void grid_barrier(int phase) {
    __syncthreads();
    if (threadIdx.x == 0) {
        __threadfence();
        unsigned arrived = atomicAdd(&g_count, 1u) + 1u;
        unsigned want = (unsigned)(phase + 1);
        if (arrived == (unsigned)NBLOCKS * want) {
            atomicExch(&g_release, want);
        } else {
            volatile unsigned* rel = &g_release;
            while (*rel < want) { __nanosleep(64); }
        }
        __threadfence();
    }
    __syncthreads();
}

// Single-instruction MUFU ops.
__device__ __forceinline__ float ex2a(float x) {
    float y; asm("ex2.approx.f32 %0, %1;" : "=f"(y) : "f"(x)); return y;
}
__device__ __forceinline__ float rcpa(float x) {
    float y; asm("rcp.approx.f32 %0, %1;" : "=f"(y) : "f"(x)); return y;
}

// 3rd largest of 8 == sorted[:, -3], branch-free FMNMX network.
__device__ __forceinline__ float theta0_of(const float v[8]) {
    float t1 = -3.4e38f, t2 = -3.4e38f, t3 = -3.4e38f;
#pragma unroll
    for (int j = 0; j < 8; j++) {
        float x  = v[j];
        float l1 = fminf(t1, x);  t1 = fmaxf(t1, x);
        float l2 = fminf(t2, l1); t2 = fmaxf(t2, l1);
        t3 = fmaxf(t3, l2);
    }
    return t3;
}

// 8 stable sigmoids, branch-free CLAMP-62 form with pair-shared reciprocals.
//   y = min(th144 - v*C100, 62)   (y = -x, exponent-clamped)
//   e = 2^y in [0, 2^62];  a = 1+e in [1, ~2^62];  m = 1/a via paired rcp.
// Pair product a0*a1 <= 2^124: always a normal float -> no R9 subnormal-flush bug.
// Clamped tail: m = 2^-62 ~ 2.2e-19 vs true smaller value (abs err <= 2e-19, nil).
// Saturated high: e -> 0 exactly, m = 1 exactly (matches fp32 sigmoid saturation).
__device__ __forceinline__ void sig8(const float v[8], float th, float m[8]) {
    float th144 = th * C100;
#pragma unroll
    for (int j = 0; j < 8; j += 2) {
        float y0 = fminf(__fmaf_rn(v[j],     -C100, th144), 62.0f);
        float y1 = fminf(__fmaf_rn(v[j + 1], -C100, th144), 62.0f);
        float e0 = ex2a(y0);
        float e1 = ex2a(y1);
        float a0 = 1.0f + e0;
        float a1 = 1.0f + e1;
        float R  = rcpa(a0 * a1);
        m[j]     = a1 * R;                 // = 1/a0
        m[j + 1] = a0 * R;                 // = 1/a1
    }
}

// f = sum(m) - 2 ; d = sum m*(1-m)
__device__ __forceinline__ void eval8(const float v[8], float th, float& f, float& d) {
    float m[8];
    sig8(v, th, m);
    float sm = 0.0f, dd = 0.0f;
#pragma unroll
    for (int j = 0; j < 8; j++) {
        sm += m[j];
        dd += __fmaf_rn(-m[j], m[j], m[j]);
    }
    f = sm - 2.0f;
    d = dd;
}

__device__ __forceinline__ float newton_adv(const float v[8], float th, float& f_out) {
    float f, d;
    eval8(v, th, f, d);
    f_out = f;
    float step = (d > 0.0f) ? 0.01f * (f * rcpa(d)) : 0.0f;
    return th + step;
}

__device__ __forceinline__ void load_row(const float* __restrict__ s, unsigned r,
                                         float v[8]) {
    const float4* p = reinterpret_cast<const float4*>(s) + (size_t)r * 2;
    float4 va = p[0];
    float4 vb = p[1];
    v[0]=va.x; v[1]=va.y; v[2]=va.z; v[3]=va.w;
    v[4]=vb.x; v[5]=vb.y; v[6]=vb.z; v[7]=vb.w;
}

__global__ void __launch_bounds__(NTHREADS, 4)
stk_fused(const float* __restrict__ s, float* __restrict__ out) {
    __shared__ float s_facc[T2CAP];
    __shared__ int   s_T;

    const int tid  = threadIdx.x;
    const int lane = tid & 31;
    const unsigned gt = blockIdx.x * NTHREADS + tid;

    for (int j = tid; j < T2CAP; j += NTHREADS) s_facc[j] = 0.0f;
    __syncthreads();

    // ======= PASS 1: uniform 7-step Newton, valid-predicated f sums, planes @5,@6 =======
    float facc[T1CAP];
#pragma unroll
    for (int t = 0; t < T1CAP; t++) facc[t] = 0.0f;

    for (int i = 0; i < RPT; i++) {
        unsigned r = gt + (unsigned)i * TOTALT;
        bool valid = (r < B_ROWS);
        unsigned rr = valid ? r : (B_ROWS - 1);   // tail lanes recompute last row

        float v[8];
        load_row(s, rr, v);

        float th = theta0_of(v);          // theta_0

#pragma unroll
        for (int t = 0; t < T1CAP; t++) {
            if (t == 5 && valid) g_th5[r] = th;   // theta_5
            if (t == 6 && valid) g_th6[r] = th;   // theta_6
            float f;
            th = newton_adv(v, th, f);
            if (valid) facc[t] += f;      // tail lanes contribute exactly 0
        }
    }

    // ---- one block reduction of facc[] ----
#pragma unroll
    for (int t = 0; t < T1CAP; t++) {
        float w = facc[t];
#pragma unroll
        for (int o = 16; o > 0; o >>= 1) w += __shfl_down_sync(0xffffffffu, w, o);
        if (lane == 0) atomicAdd(&s_facc[t], w);
    }
    __syncthreads();
    for (int j = tid; j < T1CAP; j += NTHREADS)
        atomicAdd(&g_facc[j], (double)s_facc[j]);

    grid_barrier(0);

    // ======= global stop iteration T (uniform across all blocks) =======
    if (tid == 0) {
        volatile double* fa = g_facc;
        int T = -1;
        for (int t = 0; t < T1CAP; t++) {
            if (fa[t] < SUM_TOL) { T = t; break; }   // mean<1e-3 <=> sum<4000
        }
        s_T = T;
    }
    __syncthreads();
    int T = s_T;

    // ======= COLD fallback: T > 6 (not expected; kept for safety) =======
    if (T < 0) {
        for (int j = tid; j < T2CAP; j += NTHREADS) s_facc[j] = 0.0f;
        __syncthreads();

        float facc2[T2CAP - T1CAP];
#pragma unroll
        for (int t = 0; t < T2CAP - T1CAP; t++) facc2[t] = 0.0f;

        for (int i = 0; i < RPT; i++) {
            unsigned r = gt + (unsigned)i * TOTALT;
            if (r >= B_ROWS) continue;
            float v[8];
            load_row(s, r, v);
            float th = g_th6[r];                  // theta_6
            float f;
            th = newton_adv(v, th, f);            // f(theta_6) already summed; -> theta_7
#pragma unroll
            for (int t = 0; t < T2CAP - T1CAP; t++) {
                th = newton_adv(v, th, f);        // f = f(theta_{7+t})
                facc2[t] += f;
            }
        }
#pragma unroll
        for (int t = 0; t < T2CAP - T1CAP; t++) {
            float w = facc2[t];
#pragma unroll
            for (int o = 16; o > 0; o >>= 1) w += __shfl_down_sync(0xffffffffu, w, o);
            if (lane == 0) atomicAdd(&s_facc[t], w);
        }
        __syncthreads();
        for (int j = tid; j < T2CAP - T1CAP; j += NTHREADS)
            atomicAdd(&g_facc[T1CAP + j], (double)s_facc[j]);

        grid_barrier(1);

        if (tid == 0) {
            volatile double* fa = g_facc;
            int TT = T2CAP - 1;
            for (int t = T1CAP; t < T2CAP; t++) {
                if (fa[t] < SUM_TOL) { TT = t; break; }
            }
            s_T = TT;
        }
        __syncthreads();
        T = s_T;
    }

    // checkpoint plane selection (uniform)
    const float* plane;
    int p;
    if      (T >= 6) { plane = g_th6; p = 6; }
    else if (T == 5) { plane = g_th5; p = 5; }
    else             { plane = 0;     p = 0; }

    // ======= PASS 2: resume from checkpoint (0 evals when T=6) + output =======
    for (int i = 0; i < RPT; i++) {
        unsigned r = gt + (unsigned)i * TOTALT;
        if (r >= B_ROWS) break;
        float v[8];
        load_row(s, r, v);

        float th = plane ? __ldcs(plane + r) : theta0_of(v);
        for (int t = p; t < T; t++) {
            float f;
            th = newton_adv(v, th, f);
        }

        float m[8];
        sig8(v, th, m);
        float4* q = reinterpret_cast<float4*>(out) + (size_t)r * 2;
        __stcs(q,     make_float4(m[0], m[1], m[2], m[3]));
        __stcs(q + 1, make_float4(m[4], m[5], m[6], m[7]));
    }
}

extern "C" void kernel_launch(void* const* d_in, const int* in_sizes, int n_in,
                              void* d_out, int out_size) {
    (void)in_sizes; (void)n_in; (void)out_size;
    const float* s = (const float*)d_in[0];
    float* out = (float*)d_out;

    stk_init<<<1, 256>>>();
    stk_fused<<<NBLOCKS, NTHREADS>>>(s, out);
}

// round 13
// speedup vs baseline: 3.3205x; 1.1009x over previous
#include <cuda_runtime.h>
#include <cstdint>

#define NBLOCKS   592
#define NTHREADS  256
#define TOTALT    (NBLOCKS * NTHREADS)               // 151552
#define B_ROWS    4000000
#define RPT       ((B_ROWS + TOTALT - 1) / TOTALT)   // 27
#define T1E       6                                   // pass-1 evals (sums t=0..5)
#define T2CAP     24                                  // cold fallback limit
#define C100      144.2695040888963f                 // 100 * log2(e)
#define SUM_TOL   4000.0                             // B_ROWS * 1e-3

// ---- device-global state (reset by stk_init each launch -> graph-replay safe) ----
__device__ double       g_facc[T2CAP];
__device__ unsigned int g_count;
__device__ unsigned int g_release;
__device__ float        g_th6[B_ROWS];   // theta after 6 Newton steps

__global__ void stk_init() {
    int i = threadIdx.x;
    for (int j = i; j < T2CAP; j += blockDim.x) g_facc[j] = 0.0;
    if (i == 0) { g_count = 0u; g_release = 0u; }
}

// Phase-counted software grid barrier; grid fully co-resident
// (<=64 regs via launch bounds, 4 blk/SM * 148 SMs = 592 blocks).
__device__ __forceinline__ void grid_barrier(int phase) {
    __syncthreads();
    if (threadIdx.x == 0) {
        __threadfence();
        unsigned arrived = atomicAdd(&g_count, 1u) + 1u;
        unsigned want = (unsigned)(phase + 1);
        if (arrived == (unsigned)NBLOCKS * want) {
            atomicExch(&g_release, want);
        } else {
            volatile unsigned* rel = &g_release;
            while (*rel < want) { __nanosleep(64); }
        }
        __threadfence();
    }
    __syncthreads();
}

// Single-instruction MUFU ops.
__device__ __forceinline__ float ex2a(float x) {
    float y; asm("ex2.approx.f32 %0, %1;" : "=f"(y) : "f"(x)); return y;
}
__device__ __forceinline__ float rcpa(float x) {
    float y; asm("rcp.approx.f32 %0, %1;" : "=f"(y) : "f"(x)); return y;
}

// 3rd largest of 8 == sorted[:, -3], branch-free FMNMX network.
__device__ __forceinline__ float theta0_of(const float v[8]) {
    float t1 = -3.4e38f, t2 = -3.4e38f, t3 = -3.4e38f;
#pragma unroll
    for (int j = 0; j < 8; j++) {
        float x  = v[j];
        float l1 = fminf(t1, x);  t1 = fmaxf(t1, x);
        float l2 = fminf(t2, l1); t2 = fmaxf(t2, l1);
        t3 = fmaxf(t3, l2);
    }
    return t3;
}

// 8 stable sigmoids, branch-free CLAMP-30 form, ONE rcp per 4 elements.
//   y = min(th144 - v*C100, 30);  e = 2^y <= 2^30;  a = 1+e <= ~2^30;  m = 1/a.
// 4-product <= 2^120: always a normal float (this is what broke R9 at clamp-126;
// clamp-30 is provably safe). Clamp tail: m = ~2^-30 (abs err <= 9.3e-10, nil).
// Saturated high: e -> 0 exactly, m = 1 exactly.
__device__ __forceinline__ void sig8(const float v[8], float th, float m[8]) {
    float th144 = th * C100;
#pragma unroll
    for (int g = 0; g < 8; g += 4) {
        float y0 = fminf(__fmaf_rn(v[g],     -C100, th144), 30.0f);
        float y1 = fminf(__fmaf_rn(v[g + 1], -C100, th144), 30.0f);
        float y2 = fminf(__fmaf_rn(v[g + 2], -C100, th144), 30.0f);
        float y3 = fminf(__fmaf_rn(v[g + 3], -C100, th144), 30.0f);
        float a0 = 1.0f + ex2a(y0);
        float a1 = 1.0f + ex2a(y1);
        float a2 = 1.0f + ex2a(y2);
        float a3 = 1.0f + ex2a(y3);
        float a01 = a0 * a1, a23 = a2 * a3;
        float R   = rcpa(a01 * a23);       // product in [1, 2^120]: safe
        float b01 = a23 * R;               // = 1/a01
        float b23 = a01 * R;               // = 1/a23
        m[g]     = a1 * b01;               // = 1/a0
        m[g + 1] = a0 * b01;
        m[g + 2] = a3 * b23;
        m[g + 3] = a2 * b23;
    }
}

// f = sum(m) - 2 ; d = sum m*(1-m)
__device__ __forceinline__ void eval8(const float v[8], float th, float& f, float& d) {
    float m[8];
    sig8(v, th, m);
    float sm = 0.0f, dd = 0.0f;
#pragma unroll
    for (int j = 0; j < 8; j++) {
        sm += m[j];
        dd += __fmaf_rn(-m[j], m[j], m[j]);
    }
    f = sm - 2.0f;
    d = dd;
}

__device__ __forceinline__ float newton_adv(const float v[8], float th, float& f_out) {
    float f, d;
    eval8(v, th, f, d);
    f_out = f;
    float step = (d > 0.0f) ? 0.01f * (f * rcpa(d)) : 0.0f;
    return th + step;
}

__device__ __forceinline__ void load_row(const float* __restrict__ s, unsigned r,
                                         float v[8]) {
    const float4* p = reinterpret_cast<const float4*>(s) + (size_t)r * 2;
    float4 va = p[0];
    float4 vb = p[1];
    v[0]=va.x; v[1]=va.y; v[2]=va.z; v[3]=va.w;
    v[4]=vb.x; v[5]=vb.y; v[6]=vb.z; v[7]=vb.w;
}

// block-reduce one float into s_slot (shared), then caller flushes
__device__ __forceinline__ void block_add(float w, float* s_slot, int lane) {
#pragma unroll
    for (int o = 16; o > 0; o >>= 1) w += __shfl_down_sync(0xffffffffu, w, o);
    if (lane == 0) atomicAdd(s_slot, w);
}

__global__ void __launch_bounds__(NTHREADS, 4)
stk_fused(const float* __restrict__ s, float* __restrict__ out) {
    __shared__ float s_facc[T2CAP];
    __shared__ int   s_T;

    const int tid  = threadIdx.x;
    const int lane = tid & 31;
    const unsigned gt = blockIdx.x * NTHREADS + tid;

    for (int j = tid; j < T2CAP; j += NTHREADS) s_facc[j] = 0.0f;
    __syncthreads();

    // ======= PASS 1: uniform 6-step Newton, f sums t=0..5, theta_6 plane =======
    float facc[T1E];
#pragma unroll
    for (int t = 0; t < T1E; t++) facc[t] = 0.0f;

    for (int i = 0; i < RPT; i++) {
        unsigned r = gt + (unsigned)i * TOTALT;
        bool valid = (r < B_ROWS);
        unsigned rr = valid ? r : (B_ROWS - 1);   // tail lanes recompute last row

        float v[8];
        load_row(s, rr, v);

        float th = theta0_of(v);          // theta_0
#pragma unroll
        for (int t = 0; t < T1E; t++) {
            float f;
            th = newton_adv(v, th, f);    // f(theta_t), -> theta_{t+1}
            if (valid) facc[t] += f;      // tail lanes contribute exactly 0
        }
        if (valid) g_th6[r] = th;         // theta_6
    }

#pragma unroll
    for (int t = 0; t < T1E; t++) block_add(facc[t], &s_facc[t], lane);
    __syncthreads();
    for (int j = tid; j < T1E; j += NTHREADS)
        atomicAdd(&g_facc[j], (double)s_facc[j]);

    grid_barrier(0);

    // ======= check T <= 5 (uniform; not expected) =======
    if (tid == 0) {
        volatile double* fa = g_facc;
        int T = 6;                                // tentative: T >= 6
        for (int t = 0; t < T1E; t++)
            if (fa[t] < SUM_TOL) { T = t; break; }
        s_T = T;
    }
    __syncthreads();
    int T = s_T;

    if (T < 6) {
        // ---- cold: T <= 5. Replay T steps from theta_0, output. Done. ----
        for (int i = 0; i < RPT; i++) {
            unsigned r = gt + (unsigned)i * TOTALT;
            if (r >= B_ROWS) break;
            float v[8];
            load_row(s, r, v);
            float th = theta0_of(v);
            for (int t = 0; t < T; t++) { float f; th = newton_adv(v, th, f); }
            float m[8];
            sig8(v, th, m);
            float4* q = reinterpret_cast<float4*>(out) + (size_t)r * 2;
            __stcs(q,     make_float4(m[0], m[1], m[2], m[3]));
            __stcs(q + 1, make_float4(m[4], m[5], m[6], m[7]));
        }
        return;
    }

    // ======= PASS 2 (hot): sig8 at theta_6 = output AND f(theta_6) for T=6 check =======
    {
        float f6 = 0.0f;
        for (int i = 0; i < RPT; i++) {
            unsigned r = gt + (unsigned)i * TOTALT;
            if (r >= B_ROWS) break;
            float v[8];
            load_row(s, r, v);
            float th = __ldcs(g_th6 + r);
            float m[8];
            sig8(v, th, m);
            float sm = 0.0f;
#pragma unroll
            for (int j = 0; j < 8; j++) sm += m[j];
            f6 += sm - 2.0f;                       // f(theta_6)
            float4* q = reinterpret_cast<float4*>(out) + (size_t)r * 2;
            __stcs(q,     make_float4(m[0], m[1], m[2], m[3]));
            __stcs(q + 1, make_float4(m[4], m[5], m[6], m[7]));
        }
        block_add(f6, &s_facc[T1E], lane);
        __syncthreads();
        if (tid == 0) atomicAdd(&g_facc[T1E], (double)s_facc[T1E]);
    }

    grid_barrier(1);

    // verify T == 6
    bool ok6;
    {
        volatile double* fa = g_facc;
        ok6 = (fa[T1E] < SUM_TOL);
    }
    if (ok6) return;                               // hot exit: output already correct

    // ======= COLD: T >= 7. Extend sums from theta_6, decide T, overwrite output. =======
    {
        for (int j = tid; j < T2CAP; j += NTHREADS) s_facc[j] = 0.0f;
        __syncthreads();

        float facc2[T2CAP - 7];
#pragma unroll
        for (int t = 0; t < T2CAP - 7; t++) facc2[t] = 0.0f;

        for (int i = 0; i < RPT; i++) {
            unsigned r = gt + (unsigned)i * TOTALT;
            if (r >= B_ROWS) continue;
            float v[8];
            load_row(s, r, v);
            float th = g_th6[r];
            float f;
            th = newton_adv(v, th, f);             // f(theta_6) already summed; -> theta_7
#pragma unroll
            for (int t = 0; t < T2CAP - 7; t++) {
                th = newton_adv(v, th, f);         // f(theta_{7+t})
                facc2[t] += f;
            }
        }
#pragma unroll
        for (int t = 0; t < T2CAP - 7; t++) block_add(facc2[t], &s_facc[t], lane);
        __syncthreads();
        for (int j = tid; j < T2CAP - 7; j += NTHREADS)
            atomicAdd(&g_facc[7 + j], (double)s_facc[j]);

        grid_barrier(2);

        if (tid == 0) {
            volatile double* fa = g_facc;
            int TT = T2CAP - 1;
            for (int t = 7; t < T2CAP; t++)
                if (fa[t] < SUM_TOL) { TT = t; break; }
            s_T = TT;
        }
        __syncthreads();
        T = s_T;

        for (int i = 0; i < RPT; i++) {
            unsigned r = gt + (unsigned)i * TOTALT;
            if (r >= B_ROWS) break;
            float v[8];
            load_row(s, r, v);
            float th = g_th6[r];
            for (int t = 6; t < T; t++) { float f; th = newton_adv(v, th, f); }
            float m[8];
            sig8(v, th, m);
            float4* q = reinterpret_cast<float4*>(out) + (size_t)r * 2;
            __stcs(q,     make_float4(m[0], m[1], m[2], m[3]));
            __stcs(q + 1, make_float4(m[4], m[5], m[6], m[7]));
        }
    }
}

extern "C" void kernel_launch(void* const* d_in, const int* in_sizes, int n_in,
                              void* d_out, int out_size) {
    (void)in_sizes; (void)n_in; (void)out_size;
    const float* s = (const float*)d_in[0];
    float* out = (float*)d_out;

    stk_init<<<1, 256>>>();
    stk_fused<<<NBLOCKS, NTHREADS>>>(s, out);
}

// round 16
// speedup vs baseline: 3.5612x; 1.0725x over previous
#include <cuda_runtime.h>
#include <cstdint>

#define NBLOCKS   592
#define NTHREADS  256
#define TOTALT    (NBLOCKS * NTHREADS)               // 151552
#define B_ROWS    4000000
#define RPT       ((B_ROWS + TOTALT - 1) / TOTALT)   // 27
#define T1E       6                                   // pass-1 evals (sums t=0..5)
#define T2CAP     24                                  // cold fallback limit
#define C100      144.2695040888963f                 // 100 * log2(e)
#define SUM_TOL   4000.0                             // B_ROWS * 1e-3

typedef unsigned long long u64;

// ---- device-global state (reset by stk_init each launch -> graph-replay safe) ----
__device__ double       g_facc[T2CAP];
__device__ unsigned int g_count;
__device__ unsigned int g_release;
__device__ float        g_th6[B_ROWS];   // theta after 6 Newton steps

__global__ void stk_init() {
    int i = threadIdx.x;
    for (int j = i; j < T2CAP; j += blockDim.x) g_facc[j] = 0.0;
    if (i == 0) { g_count = 0u; g_release = 0u; }
}

// Phase-counted software grid barrier; grid fully co-resident
// (<=64 regs via launch bounds, 4 blk/SM * 148 SMs = 592 blocks).
__device__ __forceinline__ void grid_barrier(int phase) {
    __syncthreads();
    if (threadIdx.x == 0) {
        __threadfence();
        unsigned arrived = atomicAdd(&g_count, 1u) + 1u;
        unsigned want = (unsigned)(phase + 1);
        if (arrived == (unsigned)NBLOCKS * want) {
            atomicExch(&g_release, want);
        } else {
            volatile unsigned* rel = &g_release;
            while (*rel < want) { __nanosleep(64); }
        }
        __threadfence();
    }
    __syncthreads();
}

// ---- single-instruction MUFU ops ----
__device__ __forceinline__ float ex2a(float x) {
    float y; asm("ex2.approx.f32 %0, %1;" : "=f"(y) : "f"(x)); return y;
}
__device__ __forceinline__ float rcpa(float x) {
    float y; asm("rcp.approx.f32 %0, %1;" : "=f"(y) : "f"(x)); return y;
}

// ---- packed f32x2 ops (identical .rn rounding per lane; 2 fp32 ops / instr) ----
__device__ __forceinline__ u64 pk2(float lo, float hi) {
    u64 r; asm("mov.b64 %0, {%1, %2};" : "=l"(r) : "f"(lo), "f"(hi)); return r;
}
__device__ __forceinline__ void up2(u64 p, float& lo, float& hi) {
    asm("mov.b64 {%0, %1}, %2;" : "=f"(lo), "=f"(hi) : "l"(p));
}
__device__ __forceinline__ u64 add2(u64 a, u64 b) {
    u64 r; asm("add.rn.f32x2 %0, %1, %2;" : "=l"(r) : "l"(a), "l"(b)); return r;
}
__device__ __forceinline__ u64 mul2(u64 a, u64 b) {
    u64 r; asm("mul.rn.f32x2 %0, %1, %2;" : "=l"(r) : "l"(a), "l"(b)); return r;
}
__device__ __forceinline__ u64 fma2_(u64 a, u64 b, u64 c) {
    u64 r; asm("fma.rn.f32x2 %0, %1, %2, %3;" : "=l"(r) : "l"(a), "l"(b), "l"(c)); return r;
}

// 3rd largest of 8 == sorted[:, -3], branch-free FMNMX network.
__device__ __forceinline__ float theta0_of(const float v[8]) {
    float t1 = -3.4e38f, t2 = -3.4e38f, t3 = -3.4e38f;
#pragma unroll
    for (int j = 0; j < 8; j++) {
        float x  = v[j];
        float l1 = fminf(t1, x);  t1 = fmaxf(t1, x);
        float l2 = fminf(t2, l1); t2 = fmaxf(t2, l1);
        t3 = fmaxf(t3, l2);
    }
    return t3;
}

// 8 stable sigmoids, CLAMP-30 + paired-rcp, packed across element groups:
// pair k holds (element k, element k+4) in (lo, hi).
// vc[k] = (v[k]*-C100, v[k+4]*-C100) precomputed once per row.
// m2[k] = (sigmoid_k, sigmoid_{k+4}).
__device__ __forceinline__ void sig8p(const u64 vc[4], float th, u64 m2[4]) {
    float th144 = th * C100;
    u64 th2 = pk2(th144, th144);
    float e[8];
#pragma unroll
    for (int k = 0; k < 4; k++) {
        u64 y2 = add2(vc[k], th2);             // y = th144 - v*C100
        float ya, yb; up2(y2, ya, yb);
        e[k]     = ex2a(fminf(ya, 30.0f));     // 2^y, exponent-clamped
        e[k + 4] = ex2a(fminf(yb, 30.0f));
    }
    const u64 ONE2 = pk2(1.0f, 1.0f);
    u64 a0 = add2(pk2(e[0], e[4]), ONE2);      // a = 1+e in [1, ~2^30]
    u64 a1 = add2(pk2(e[1], e[5]), ONE2);
    u64 a2 = add2(pk2(e[2], e[6]), ONE2);
    u64 a3 = add2(pk2(e[3], e[7]), ONE2);
    u64 a01 = mul2(a0, a1);
    u64 a23 = mul2(a2, a3);
    u64 P   = mul2(a01, a23);                  // <= 2^120 per lane: always normal
    float pa, pb; up2(P, pa, pb);
    u64 R   = pk2(rcpa(pa), rcpa(pb));
    u64 b01 = mul2(a23, R);                    // = 1/a01
    u64 b23 = mul2(a01, R);                    // = 1/a23
    m2[0] = mul2(a1, b01);                     // = 1/a0
    m2[1] = mul2(a0, b01);
    m2[2] = mul2(a3, b23);
    m2[3] = mul2(a2, b23);
}

// f = sum(m) - 2 ; d = sum m - sum m^2 = sum m*(1-m)
__device__ __forceinline__ void eval8p(const u64 vc[4], float th, float& f, float& d) {
    u64 m2[4];
    sig8p(vc, th, m2);
    u64 sm = add2(add2(m2[0], m2[1]), add2(m2[2], m2[3]));
    u64 q  = mul2(m2[0], m2[0]);
    q = fma2_(m2[1], m2[1], q);
    q = fma2_(m2[2], m2[2], q);
    q = fma2_(m2[3], m2[3], q);
    float sa, sb, qa, qb;
    up2(sm, sa, sb);
    up2(q,  qa, qb);
    f = (sa + sb) - 2.0f;
    d = (sa - qa) + (sb - qb);
}

__device__ __forceinline__ float newton_advp(const u64 vc[4], float th, float& f_out) {
    float f, d;
    eval8p(vc, th, f, d);
    f_out = f;
    float step = (d > 0.0f) ? 0.01f * (f * rcpa(d)) : 0.0f;
    return th + step;
}

// load row, fill scalar v[8] and packed vc[4]
__device__ __forceinline__ void load_row(const float* __restrict__ s, unsigned r,
                                         float v[8], u64 vc[4]) {
    const float4* p = reinterpret_cast<const float4*>(s) + (size_t)r * 2;
    float4 va = p[0];
    float4 vb = p[1];
    v[0]=va.x; v[1]=va.y; v[2]=va.z; v[3]=va.w;
    v[4]=vb.x; v[5]=vb.y; v[6]=vb.z; v[7]=vb.w;
    vc[0] = pk2(va.x * -C100, vb.x * -C100);
    vc[1] = pk2(va.y * -C100, vb.y * -C100);
    vc[2] = pk2(va.z * -C100, vb.z * -C100);
    vc[3] = pk2(va.w * -C100, vb.w * -C100);
}

__device__ __forceinline__ void store_out(float* __restrict__ out, unsigned r,
                                          const u64 m2[4]) {
    float m0, m4, m1, m5, m3, m7, mm2, m6;
    up2(m2[0], m0, m4);
    up2(m2[1], m1, m5);
    up2(m2[2], mm2, m6);
    up2(m2[3], m3, m7);
    float4* q = reinterpret_cast<float4*>(out) + (size_t)r * 2;
    __stcs(q,     make_float4(m0, m1, mm2, m3));
    __stcs(q + 1, make_float4(m4, m5, m6, m7));
}

// block-reduce one float into s_slot (shared)
__device__ __forceinline__ void block_add(float w, float* s_slot, int lane) {
#pragma unroll
    for (int o = 16; o > 0; o >>= 1) w += __shfl_down_sync(0xffffffffu, w, o);
    if (lane == 0) atomicAdd(s_slot, w);
}

__global__ void __launch_bounds__(NTHREADS, 4)
stk_fused(const float* __restrict__ s, float* __restrict__ out) {
    __shared__ float s_facc[T2CAP];
    __shared__ int   s_T;

    const int tid  = threadIdx.x;
    const int lane = tid & 31;
    const unsigned gt = blockIdx.x * NTHREADS + tid;

    for (int j = tid; j < T2CAP; j += NTHREADS) s_facc[j] = 0.0f;
    __syncthreads();

    // ======= PASS 1: uniform 6-step Newton (packed), f sums t=0..5, theta_6 plane =======
    float facc[T1E];
#pragma unroll
    for (int t = 0; t < T1E; t++) facc[t] = 0.0f;

    for (int i = 0; i < RPT; i++) {
        unsigned r = gt + (unsigned)i * TOTALT;
        bool valid = (r < B_ROWS);
        unsigned rr = valid ? r : (B_ROWS - 1);   // tail lanes recompute last row

        float v[8]; u64 vc[4];
        load_row(s, rr, v, vc);

        float th = theta0_of(v);          // theta_0
#pragma unroll
        for (int t = 0; t < T1E; t++) {
            float f;
            th = newton_advp(vc, th, f);  // f(theta_t), -> theta_{t+1}
            if (valid) facc[t] += f;      // tail lanes contribute exactly 0
        }
        if (valid) g_th6[r] = th;         // theta_6
    }

#pragma unroll
    for (int t = 0; t < T1E; t++) block_add(facc[t], &s_facc[t], lane);
    __syncthreads();
    for (int j = tid; j < T1E; j += NTHREADS)
        atomicAdd(&g_facc[j], (double)s_facc[j]);

    grid_barrier(0);

    // ======= check T <= 5 (uniform; not expected) =======
    if (tid == 0) {
        volatile double* fa = g_facc;
        int T = 6;                                // tentative: T >= 6
        for (int t = 0; t < T1E; t++)
            if (fa[t] < SUM_TOL) { T = t; break; }
        s_T = T;
    }
    __syncthreads();
    int T = s_T;

    if (T < 6) {
        // ---- cold: T <= 5. Replay T steps from theta_0, output. Done. ----
        for (int i = 0; i < RPT; i++) {
            unsigned r = gt + (unsigned)i * TOTALT;
            if (r >= B_ROWS) break;
            float v[8]; u64 vc[4];
            load_row(s, r, v, vc);
            float th = theta0_of(v);
            for (int t = 0; t < T; t++) { float f; th = newton_advp(vc, th, f); }
            u64 m2[4];
            sig8p(vc, th, m2);
            store_out(out, r, m2);
        }
        return;
    }

    // ======= PASS 2 (hot): sig8 at theta_6 = output AND f(theta_6) for T=6 check =======
    {
        float f6 = 0.0f;
        for (int i = 0; i < RPT; i++) {
            unsigned r = gt + (unsigned)i * TOTALT;
            if (r >= B_ROWS) break;
            float v[8]; u64 vc[4];
            load_row(s, r, v, vc);
            float th = __ldcs(g_th6 + r);
            u64 m2[4];
            sig8p(vc, th, m2);
            u64 sm = add2(add2(m2[0], m2[1]), add2(m2[2], m2[3]));
            float sa, sb; up2(sm, sa, sb);
            f6 += (sa + sb) - 2.0f;                // f(theta_6)
            store_out(out, r, m2);
        }
        block_add(f6, &s_facc[T1E], lane);
        __syncthreads();
        if (tid == 0) atomicAdd(&g_facc[T1E], (double)s_facc[T1E]);
    }

    grid_barrier(1);

    // verify T == 6
    bool ok6;
    {
        volatile double* fa = g_facc;
        ok6 = (fa[T1E] < SUM_TOL);
    }
    if (ok6) return;                               // hot exit: output already correct

    // ======= COLD: T >= 7. Extend sums from theta_6, decide T, overwrite output. =======
    {
        for (int j = tid; j < T2CAP; j += NTHREADS) s_facc[j] = 0.0f;
        __syncthreads();

        float facc2[T2CAP - 7];
#pragma unroll
        for (int t = 0; t < T2CAP - 7; t++) facc2[t] = 0.0f;

        for (int i = 0; i < RPT; i++) {
            unsigned r = gt + (unsigned)i * TOTALT;
            if (r >= B_ROWS) continue;
            float v[8]; u64 vc[4];
            load_row(s, r, v, vc);
            float th = g_th6[r];
            float f;
            th = newton_advp(vc, th, f);           // f(theta_6) already summed; -> theta_7
#pragma unroll
            for (int t = 0; t < T2CAP - 7; t++) {
                th = newton_advp(vc, th, f);       // f(theta_{7+t})
                facc2[t] += f;
            }
        }
#pragma unroll
        for (int t = 0; t < T2CAP - 7; t++) block_add(facc2[t], &s_facc[t], lane);
        __syncthreads();
        for (int j = tid; j < T2CAP - 7; j += NTHREADS)
            atomicAdd(&g_facc[7 + j], (double)s_facc[j]);

        grid_barrier(2);

        if (tid == 0) {
            volatile double* fa = g_facc;
            int TT = T2CAP - 1;
            for (int t = 7; t < T2CAP; t++)
                if (fa[t] < SUM_TOL) { TT = t; break; }
            s_T = TT;
        }
        __syncthreads();
        T = s_T;

        for (int i = 0; i < RPT; i++) {
            unsigned r = gt + (unsigned)i * TOTALT;
            if (r >= B_ROWS) break;
            float v[8]; u64 vc[4];
            load_row(s, r, v, vc);
            float th = g_th6[r];
            for (int t = 6; t < T; t++) { float f; th = newton_advp(vc, th, f); }
            u64 m2[4];
            sig8p(vc, th, m2);
            store_out(out, r, m2);
        }
    }
}

extern "C" void kernel_launch(void* const* d_in, const int* in_sizes, int n_in,
                              void* d_out, int out_size) {
    (void)in_sizes; (void)n_in; (void)out_size;
    const float* s = (const float*)d_in[0];
    float* out = (float*)d_out;

    stk_init<<<1, 256>>>();
    stk_fused<<<NBLOCKS, NTHREADS>>>(s, out);
}

// round 17
// speedup vs baseline: 4.4304x; 1.2441x over previous
#include <cuda_runtime.h>
#include <cstdint>

#define NBLOCKS   592
#define NTHREADS  256
#define TOTALT    (NBLOCKS * NTHREADS)               // 151552
#define B_ROWS    4000000
#define RPT       ((B_ROWS + TOTALT - 1) / TOTALT)   // 27
#define T1E       6                                   // Newton steps in hot path
#define T2CAP     24                                  // cold fallback limit
#define C100      144.2695040888963f                 // 100 * log2(e)
#define SUM_TOL   4000.0                             // B_ROWS * 1e-3

typedef unsigned long long u64;

// ---- device-global state (reset by stk_init each launch -> graph-replay safe) ----
__device__ double       g_facc[T2CAP];
__device__ unsigned int g_count;
__device__ unsigned int g_release;
__device__ float        g_th6[B_ROWS];   // used only by the cold T>=7 path

__global__ void stk_init() {
    int i = threadIdx.x;
    for (int j = i; j < T2CAP; j += blockDim.x) g_facc[j] = 0.0;
    if (i == 0) { g_count = 0u; g_release = 0u; }
}

// Phase-counted software grid barrier; grid fully co-resident
// (<=64 regs via launch bounds, 4 blk/SM * 148 SMs = 592 blocks).
__device__ __forceinline__ void grid_barrier(int phase) {
    __syncthreads();
    if (threadIdx.x == 0) {
        __threadfence();
        unsigned arrived = atomicAdd(&g_count, 1u) + 1u;
        unsigned want = (unsigned)(phase + 1);
        if (arrived == (unsigned)NBLOCKS * want) {
            atomicExch(&g_release, want);
        } else {
            volatile unsigned* rel = &g_release;
            while (*rel < want) { __nanosleep(64); }
        }
        __threadfence();
    }
    __syncthreads();
}

// ---- single-instruction MUFU ops ----
__device__ __forceinline__ float ex2a(float x) {
    float y; asm("ex2.approx.f32 %0, %1;" : "=f"(y) : "f"(x)); return y;
}
__device__ __forceinline__ float rcpa(float x) {
    float y; asm("rcp.approx.f32 %0, %1;" : "=f"(y) : "f"(x)); return y;
}

// ---- packed f32x2 ops ----
__device__ __forceinline__ u64 pk2(float lo, float hi) {
    u64 r; asm("mov.b64 %0, {%1, %2};" : "=l"(r) : "f"(lo), "f"(hi)); return r;
}
__device__ __forceinline__ void up2(u64 p, float& lo, float& hi) {
    asm("mov.b64 {%0, %1}, %2;" : "=f"(lo), "=f"(hi) : "l"(p));
}
__device__ __forceinline__ u64 add2(u64 a, u64 b) {
    u64 r; asm("add.rn.f32x2 %0, %1, %2;" : "=l"(r) : "l"(a), "l"(b)); return r;
}
__device__ __forceinline__ u64 mul2(u64 a, u64 b) {
    u64 r; asm("mul.rn.f32x2 %0, %1, %2;" : "=l"(r) : "l"(a), "l"(b)); return r;
}
__device__ __forceinline__ u64 fma2_(u64 a, u64 b, u64 c) {
    u64 r; asm("fma.rn.f32x2 %0, %1, %2, %3;" : "=l"(r) : "l"(a), "l"(b), "l"(c)); return r;
}

// 3rd largest of 8 == sorted[:, -3], branch-free FMNMX network.
__device__ __forceinline__ float theta0_of(const float v[8]) {
    float t1 = -3.4e38f, t2 = -3.4e38f, t3 = -3.4e38f;
#pragma unroll
    for (int j = 0; j < 8; j++) {
        float x  = v[j];
        float l1 = fminf(t1, x);  t1 = fmaxf(t1, x);
        float l2 = fminf(t2, l1); t2 = fmaxf(t2, l1);
        t3 = fmaxf(t3, l2);
    }
    return t3;
}

// 8 stable sigmoids, CLAMP-30 + paired-rcp, packed: pair k = (elem k, elem k+4).
__device__ __forceinline__ void sig8p(const u64 vc[4], float th, u64 m2[4]) {
    float th144 = th * C100;
    u64 th2 = pk2(th144, th144);
    float e[8];
#pragma unroll
    for (int k = 0; k < 4; k++) {
        u64 y2 = add2(vc[k], th2);             // y = th144 - v*C100
        float ya, yb; up2(y2, ya, yb);
        e[k]     = ex2a(fminf(ya, 30.0f));     // 2^y, exponent-clamped
        e[k + 4] = ex2a(fminf(yb, 30.0f));
    }
    const u64 ONE2 = pk2(1.0f, 1.0f);
    u64 a0 = add2(pk2(e[0], e[4]), ONE2);      // a = 1+e in [1, ~2^30]
    u64 a1 = add2(pk2(e[1], e[5]), ONE2);
    u64 a2 = add2(pk2(e[2], e[6]), ONE2);
    u64 a3 = add2(pk2(e[3], e[7]), ONE2);
    u64 a01 = mul2(a0, a1);
    u64 a23 = mul2(a2, a3);
    u64 P   = mul2(a01, a23);                  // <= 2^120 per lane: always normal
    float pa, pb; up2(P, pa, pb);
    u64 R   = pk2(rcpa(pa), rcpa(pb));
    u64 b01 = mul2(a23, R);                    // = 1/a01
    u64 b23 = mul2(a01, R);                    // = 1/a23
    m2[0] = mul2(a1, b01);                     // = 1/a0
    m2[1] = mul2(a0, b01);
    m2[2] = mul2(a3, b23);
    m2[3] = mul2(a2, b23);
}

// f = sum(m) - 2 ; d = sum m - sum m^2 = sum m*(1-m)
__device__ __forceinline__ void eval8p(const u64 vc[4], float th, float& f, float& d) {
    u64 m2[4];
    sig8p(vc, th, m2);
    u64 sm = add2(add2(m2[0], m2[1]), add2(m2[2], m2[3]));
    u64 q  = mul2(m2[0], m2[0]);
    q = fma2_(m2[1], m2[1], q);
    q = fma2_(m2[2], m2[2], q);
    q = fma2_(m2[3], m2[3], q);
    float sa, sb, qa, qb;
    up2(sm, sa, sb);
    up2(q,  qa, qb);
    f = (sa + sb) - 2.0f;
    d = (sa - qa) + (sb - qb);
}

__device__ __forceinline__ float newton_advp(const u64 vc[4], float th, float& f_out) {
    float f, d;
    eval8p(vc, th, f, d);
    f_out = f;
    float step = (d > 0.0f) ? 0.01f * (f * rcpa(d)) : 0.0f;
    return th + step;
}

__device__ __forceinline__ void load_row(const float* __restrict__ s, unsigned r,
                                         float v[8], u64 vc[4]) {
    const float4* p = reinterpret_cast<const float4*>(s) + (size_t)r * 2;
    float4 va = p[0];
    float4 vb = p[1];
    v[0]=va.x; v[1]=va.y; v[2]=va.z; v[3]=va.w;
    v[4]=vb.x; v[5]=vb.y; v[6]=vb.z; v[7]=vb.w;
    vc[0] = pk2(va.x * -C100, vb.x * -C100);
    vc[1] = pk2(va.y * -C100, vb.y * -C100);
    vc[2] = pk2(va.z * -C100, vb.z * -C100);
    vc[3] = pk2(va.w * -C100, vb.w * -C100);
}

__device__ __forceinline__ void store_out(float* __restrict__ out, unsigned r,
                                          const u64 m2[4]) {
    float m0, m4, m1, m5, m3, m7, mm2, m6;
    up2(m2[0], m0, m4);
    up2(m2[1], m1, m5);
    up2(m2[2], mm2, m6);
    up2(m2[3], m3, m7);
    float4* q = reinterpret_cast<float4*>(out) + (size_t)r * 2;
    __stcs(q,     make_float4(m0, m1, mm2, m3));
    __stcs(q + 1, make_float4(m4, m5, m6, m7));
}

// block-reduce one float into s_slot (shared)
__device__ __forceinline__ void block_add(float w, float* s_slot, int lane) {
#pragma unroll
    for (int o = 16; o > 0; o >>= 1) w += __shfl_down_sync(0xffffffffu, w, o);
    if (lane == 0) atomicAdd(s_slot, w);
}

__global__ void __launch_bounds__(NTHREADS, 4)
stk_fused(const float* __restrict__ s, float* __restrict__ out) {
    __shared__ float s_facc[T2CAP];
    __shared__ int   s_T;

    const int tid  = threadIdx.x;
    const int lane = tid & 31;
    const unsigned gt = blockIdx.x * NTHREADS + tid;

    for (int j = tid; j < T2CAP; j += NTHREADS) s_facc[j] = 0.0f;
    __syncthreads();

    // ======= FUSED HOT PASS: 6 Newton steps + optimistic output at theta_6 =======
    // f sums for t=0..6 accumulate for the T decision; output is written NOW and
    // only overwritten if verification fails (cold paths, never expected).
    float facc[T1E + 1];
#pragma unroll
    for (int t = 0; t <= T1E; t++) facc[t] = 0.0f;

    for (int i = 0; i < RPT; i++) {
        unsigned r = gt + (unsigned)i * TOTALT;
        bool valid = (r < B_ROWS);
        unsigned rr = valid ? r : (B_ROWS - 1);   // tail lanes recompute last row

        float v[8]; u64 vc[4];
        load_row(s, rr, v, vc);

        float th = theta0_of(v);          // theta_0
#pragma unroll
        for (int t = 0; t < T1E; t++) {
            float f;
            th = newton_advp(vc, th, f);  // f(theta_t), -> theta_{t+1}
            if (valid) facc[t] += f;      // tail lanes contribute exactly 0
        }

        // 7th sig8: output gates at theta_6 AND f(theta_6) for verification
        u64 m2[4];
        sig8p(vc, th, m2);
        u64 sm = add2(add2(m2[0], m2[1]), add2(m2[2], m2[3]));
        float sa, sb; up2(sm, sa, sb);
        if (valid) {
            facc[T1E] += (sa + sb) - 2.0f;
            store_out(out, r, m2);
        }
    }

#pragma unroll
    for (int t = 0; t <= T1E; t++) block_add(facc[t], &s_facc[t], lane);
    __syncthreads();
    for (int j = tid; j <= T1E; j += NTHREADS)
        atomicAdd(&g_facc[j], (double)s_facc[j]);

    grid_barrier(0);

    // ======= verdict: find first t in [0,6] with sum < tol =======
    if (tid == 0) {
        volatile double* fa = g_facc;
        int T = -1;                               // -1 => T >= 7
        for (int t = 0; t <= T1E; t++)
            if (fa[t] < SUM_TOL) { T = t; break; }
        s_T = T;
    }
    __syncthreads();
    int T = s_T;

    if (T == T1E) return;                         // HOT EXIT: output already correct

    // ======= COLD: T <= 5. Replay T steps from theta_0, overwrite output. =======
    if (T >= 0) {
        for (int i = 0; i < RPT; i++) {
            unsigned r = gt + (unsigned)i * TOTALT;
            if (r >= B_ROWS) break;
            float v[8]; u64 vc[4];
            load_row(s, r, v, vc);
            float th = theta0_of(v);
            for (int t = 0; t < T; t++) { float f; th = newton_advp(vc, th, f); }
            u64 m2[4];
            sig8p(vc, th, m2);
            store_out(out, r, m2);
        }
        return;
    }

    // ======= COLD: T >= 7. Recompute theta_6, extend sums, decide T, overwrite. =======
    {
        for (int j = tid; j < T2CAP; j += NTHREADS) s_facc[j] = 0.0f;
        __syncthreads();

        float facc2[T2CAP - 7];
#pragma unroll
        for (int t = 0; t < T2CAP - 7; t++) facc2[t] = 0.0f;

        for (int i = 0; i < RPT; i++) {
            unsigned r = gt + (unsigned)i * TOTALT;
            if (r >= B_ROWS) continue;
            float v[8]; u64 vc[4];
            load_row(s, r, v, vc);
            float th = theta0_of(v);
            for (int t = 0; t < T1E; t++) { float f; th = newton_advp(vc, th, f); }
            g_th6[r] = th;                         // theta_6
            float f;
            th = newton_advp(vc, th, f);           // f(theta_6) already summed; -> theta_7
#pragma unroll
            for (int t = 0; t < T2CAP - 7; t++) {
                th = newton_advp(vc, th, f);       // f(theta_{7+t})
                facc2[t] += f;
            }
        }
#pragma unroll
        for (int t = 0; t < T2CAP - 7; t++) block_add(facc2[t], &s_facc[t], lane);
        __syncthreads();
        for (int j = tid; j < T2CAP - 7; j += NTHREADS)
            atomicAdd(&g_facc[7 + j], (double)s_facc[j]);

        grid_barrier(1);

        if (tid == 0) {
            volatile double* fa = g_facc;
            int TT = T2CAP - 1;
            for (int t = 7; t < T2CAP; t++)
                if (fa[t] < SUM_TOL) { TT = t; break; }
            s_T = TT;
        }
        __syncthreads();
        T = s_T;

        for (int i = 0; i < RPT; i++) {
            unsigned r = gt + (unsigned)i * TOTALT;
            if (r >= B_ROWS) break;
            float v[8]; u64 vc[4];
            load_row(s, r, v, vc);
            float th = g_th6[r];
            for (int t = T1E; t < T; t++) { float f; th = newton_advp(vc, th, f); }
            u64 m2[4];
            sig8p(vc, th, m2);
            store_out(out, r, m2);
        }
    }
}

extern "C" void kernel_launch(void* const* d_in, const int* in_sizes, int n_in,
                              void* d_out, int out_size) {
    (void)in_sizes; (void)n_in; (void)out_size;
    const float* s = (const float*)d_in[0];
    float* out = (float*)d_out;

    stk_init<<<1, 256>>>();
    stk_fused<<<NBLOCKS, NTHREADS>>>(s, out);
}